// round 11
// baseline (speedup 1.0000x reference)
#include <cuda_runtime.h>
#include <cstddef>

// ManyBodyVoxel: out[0, a, c=t*2+l, x, y, z] =
//   sum_n exp(coeff * || grid_l[x,y,z] - d[a,n]*mask_t[a,n] ||^2)
// R11: grid=256 (a,l) x 512 thr; thread = (x, y, z-half) owns 8 voxels ->
//      10 LDS wavefronts per 256 voxel-updates, 4 indep accumulators;
//      center-out geometric recurrence for exp rows (R10).

#define NT 512

typedef unsigned long long u64;

__device__ __forceinline__ u64 pk2(float v) {
    u64 r; asm("mov.b64 %0, {%1, %2};" : "=l"(r) : "f"(v), "f"(v)); return r;
}
__device__ __forceinline__ u64 fma2(u64 a, u64 b, u64 c) {
    u64 d; asm("fma.rn.f32x2 %0, %1, %2, %3;" : "=l"(d) : "l"(a), "l"(b), "l"(c)); return d;
}
__device__ __forceinline__ u64 mul2(u64 a, u64 b) {
    u64 d; asm("mul.rn.f32x2 %0, %1, %2;" : "=l"(d) : "l"(a), "l"(b)); return d;
}

__global__ __launch_bounds__(NT, 3)
void mbv_kernel(const float* __restrict__ dist,   // (1,128,64,3) fp32
                const float* __restrict__ sigma,  // (1,) fp32
                const int*   __restrict__ anum,   // (128,64) int64 or int32 (auto-detect)
                float* __restrict__ out)          // (1,128,10,16,16,16) fp32
{
    const int a   = blockIdx.x >> 1;
    const int l   = blockIdx.x & 1;   // 0: L=8, 1: L=12
    const int tid = threadIdx.x;
    const int zh  = tid & 1;          // z half: [zh*8, zh*8+8)
    const int y   = (tid >> 1) & 15;
    const int x   = (tid >> 5) & 15;

    // Record (slot): 64 floats = 256B. x[16] @ +0, y[16] @ +64B, z[16] @ +128B.
    // Slots 0..ncls-1: classified atoms (type-major compact); slot 64: base (d=0).
    __shared__ __align__(16) float tab[65 * 64];
    __shared__ float dsm[192];
    __shared__ short ord[64];
    __shared__ int   startc[5];
    __shared__ int   cntc[5];
    __shared__ int   nclss;

    const float s  = sigma[0];
    const float cf = -0.5f / (s * s);

    // ---- Phase 0: warp0 classifies (ballot compaction); threads 32..223 stage dist ----
    if (tid < 32) {
        int4 p = ((const int4*)anum)[tid];            // probe row 0 (dtype)
        int4 q = ((const int4*)anum)[a * 32 + tid];   // int64 view
        int2 r = ((const int2*)anum)[a * 32 + tid];   // int32 view
        bool i32 = __any_sync(0xffffffffu, (p.y | p.w) != 0);
        int z0 = i32 ? r.x : q.x;
        int z1 = i32 ? r.y : q.z;
        unsigned lt = (1u << tid) - 1u;
        const int ZT[5] = {1, 6, 7, 8, 16};
        int base = 0;
        #pragma unroll
        for (int t = 0; t < 5; t++) {
            unsigned m0 = __ballot_sync(0xffffffffu, z0 == ZT[t]);
            unsigned m1 = __ballot_sync(0xffffffffu, z1 == ZT[t]);
            int c0 = __popc(m0), c = c0 + __popc(m1);
            if (z0 == ZT[t]) ord[base + __popc(m0 & lt)]      = (short)(2 * tid);
            if (z1 == ZT[t]) ord[base + c0 + __popc(m1 & lt)] = (short)(2 * tid + 1);
            if (tid == 0) { startc[t] = base; cntc[t] = c; }
            base += c;
        }
        if (tid == 0) nclss = base;
    } else if (tid < 224) {
        dsm[tid - 32] = dist[a * 192 + (tid - 32)];
    }

    __syncthreads();

    // ---- Phase 1: exp rows via center-out geometric recurrence ----
    {
        const float Lp   = l ? 12.0f : 8.0f;
        const float half = 0.5f * Lp;
        const float step = Lp * (1.0f / 15.0f);
        const float Brat = __expf(2.0f * cf * step * step);

        const int nrec = nclss + 1;
        if (tid < 3 * nrec) {                 // unit = (slot, axis), 16 ticks each
            int slot = tid / 3;
            int ax   = tid - slot * 3;
            int isbase = (slot == nclss);
            int recid  = isbase ? 64 : slot;
            float dv   = isbase ? 0.0f : dsm[(int)ord[slot] * 3 + ax];
            float* dst = &tab[recid * 64 + ax * 16];

            float bse = -half - dv;
            int jc = __float2int_rn(-bse / step);   // tick nearest Gaussian peak
            jc = max(0, min(15, jc));
            float uc = bse + step * (float)jc;
            float fc = __expf(cf * uc * uc);
            float ru = __expf(cf * step * (2.0f * uc + step));
            float rd = __expf(cf * step * (step - 2.0f * uc));
            dst[jc] = fc;
            float f = fc, r = ru;
            for (int j = jc + 1; j < 16; j++) { f *= r; r *= Brat; dst[j] = f; }
            f = fc; r = rd;
            for (int j = jc - 1; j >= 0; j--) { f *= r; r *= Brat; dst[j] = f; }
        }
    }

    __syncthreads();

    // ---- Phase 2: consumer. Thread owns 8 voxels z in [zh*8, zh*8+8) of (x,y) ----
    const char* tb = reinterpret_cast<const char*>(tab);
    const int offx = x * 4;
    const int offy = 64 + y * 4;
    const int offz = 128 + zh * 32;

    const char* br = tb + 64 * 256;   // base record
    const float bxy = *(const float*)(br + offx) * *(const float*)(br + offy);
    const ulonglong2 bqa = *(const ulonglong2*)(br + offz);
    const ulonglong2 bqb = *(const ulonglong2*)(br + offz + 16);

    // out offset (floats): (a*10 + t*2 + l)*4096 + x*256 + y*16 + zh*8
    char* op = reinterpret_cast<char*>(out)
             + ((((size_t)(a * 10 + l)) << 12) + ((size_t)x << 8) + ((size_t)y << 4) + ((size_t)zh << 3)) * 4;

    #pragma unroll
    for (int t = 0; t < 5; t++) {
        const int c  = cntc[t];
        const u64 bm = pk2((float)(64 - c) * bxy);
        u64 a0 = mul2(bm, bqa.x);
        u64 a1 = mul2(bm, bqa.y);
        u64 a2 = mul2(bm, bqb.x);
        u64 a3 = mul2(bm, bqb.y);

        const char* p = tb + startc[t] * 256;
        for (int k = 0; k < c; k++) {
            float sx = *(const float*)(p + offx);
            float sy = *(const float*)(p + offy);
            ulonglong2 qa = *(const ulonglong2*)(p + offz);
            ulonglong2 qb = *(const ulonglong2*)(p + offz + 16);
            u64 sp = pk2(sx * sy);
            a0 = fma2(sp, qa.x, a0);
            a1 = fma2(sp, qa.y, a1);
            a2 = fma2(sp, qb.x, a2);
            a3 = fma2(sp, qb.y, a3);
            p += 256;
        }

        __stcs((ulonglong2*)op,        make_ulonglong2(a0, a1));
        __stcs((ulonglong2*)(op + 16), make_ulonglong2(a2, a3));
        op += 2 * 4096 * 4;   // next type channel
    }
}

extern "C" void kernel_launch(void* const* d_in, const int* in_sizes, int n_in,
                              void* d_out, int out_size) {
    const float* dist = nullptr;
    const float* sig  = nullptr;
    const int*   an   = nullptr;
    for (int i = 0; i < n_in; i++) {
        if (in_sizes[i] == 1)          sig  = (const float*)d_in[i];
        else if (in_sizes[i] == 24576) dist = (const float*)d_in[i];
        else if (in_sizes[i] == 8192)  an   = (const int*)d_in[i];
    }
    if (!dist) dist = (const float*)d_in[0];
    if (!sig)  sig  = (const float*)d_in[1];
    if (!an)   an   = (const int*)d_in[2];

    mbv_kernel<<<256, NT>>>(dist, sig, an, (float*)d_out);
}

// round 12
// speedup vs baseline: 1.0726x; 1.0726x over previous
#include <cuda_runtime.h>
#include <cstddef>

// ManyBodyVoxel: out[0, a, c=t*2+l, x, y, z] =
//   sum_n exp(coeff * || grid_l[x,y,z] - d[a,n]*mask_t[a,n] ||^2)
// R12: thread = (y,z), registers hold 4 x-accumulators (packed f32x2 pairs).
//      X row is warp-uniform -> 1 broadcast LDS.128; per warp-atom-iter ~3
//      wavefronts + 9 instr for 128 voxel updates. grid = 1024 (a,l,xq) x 256,
//      ~87% occupancy, 7:6 balance. Exp rows by center-out recurrence (R10).

#define NT 256

typedef unsigned long long u64;

__device__ __forceinline__ u64 pk2(float v) {
    u64 r; asm("mov.b64 %0, {%1, %2};" : "=l"(r) : "f"(v), "f"(v)); return r;
}
__device__ __forceinline__ u64 fma2(u64 a, u64 b, u64 c) {
    u64 d; asm("fma.rn.f32x2 %0, %1, %2, %3;" : "=l"(d) : "l"(a), "l"(b), "l"(c)); return d;
}
__device__ __forceinline__ u64 mul2(u64 a, u64 b) {
    u64 d; asm("mul.rn.f32x2 %0, %1, %2;" : "=l"(d) : "l"(a), "l"(b)); return d;
}
__device__ __forceinline__ void unpk(u64 v, float& lo, float& hi) {
    asm("mov.b64 {%0, %1}, %2;" : "=f"(lo), "=f"(hi) : "l"(v));
}

__global__ __launch_bounds__(NT, 7)
void mbv_kernel(const float* __restrict__ dist,   // (1,128,64,3) fp32
                const float* __restrict__ sigma,  // (1,) fp32
                const int*   __restrict__ anum,   // (128,64) int64 or int32 (auto-detect)
                float* __restrict__ out)          // (1,128,10,16,16,16) fp32
{
    const int b   = blockIdx.x;
    const int xq  = b & 3;            // x quarter: this CTA covers x in [xq*4, xq*4+4)
    const int l   = (b >> 2) & 1;     // 0: L=8, 1: L=12
    const int a   = b >> 3;
    const int tid = threadIdx.x;
    const int z   = tid & 15;
    const int y   = tid >> 4;

    // Record (slot): 64 floats = 256B. x[16] @ +0, y[16] @ +64B, z[16] @ +128B.
    // Slots 0..ncls-1: classified atoms (type-major compact); slot 64: base (d=0).
    __shared__ __align__(16) float tab[65 * 64];
    __shared__ float dsm[192];
    __shared__ short ord[64];
    __shared__ int   startc[5];
    __shared__ int   cntc[5];
    __shared__ int   nclss;

    const float s  = sigma[0];
    const float cf = -0.5f / (s * s);

    // ---- Phase 0: warp0 classifies (ballot compaction); threads 32..223 stage dist ----
    if (tid < 32) {
        int4 p = ((const int4*)anum)[tid];            // probe row 0 (dtype)
        int4 q = ((const int4*)anum)[a * 32 + tid];   // int64 view
        int2 r = ((const int2*)anum)[a * 32 + tid];   // int32 view
        bool i32 = __any_sync(0xffffffffu, (p.y | p.w) != 0);
        int z0 = i32 ? r.x : q.x;
        int z1 = i32 ? r.y : q.z;
        unsigned lt = (1u << tid) - 1u;
        const int ZT[5] = {1, 6, 7, 8, 16};
        int base = 0;
        #pragma unroll
        for (int t = 0; t < 5; t++) {
            unsigned m0 = __ballot_sync(0xffffffffu, z0 == ZT[t]);
            unsigned m1 = __ballot_sync(0xffffffffu, z1 == ZT[t]);
            int c0 = __popc(m0), c = c0 + __popc(m1);
            if (z0 == ZT[t]) ord[base + __popc(m0 & lt)]      = (short)(2 * tid);
            if (z1 == ZT[t]) ord[base + c0 + __popc(m1 & lt)] = (short)(2 * tid + 1);
            if (tid == 0) { startc[t] = base; cntc[t] = c; }
            base += c;
        }
        if (tid == 0) nclss = base;
    } else if (tid < 224) {
        dsm[tid - 32] = dist[a * 192 + (tid - 32)];
    }

    __syncthreads();

    // ---- Phase 1: exp rows via center-out geometric recurrence ----
    {
        const float Lp   = l ? 12.0f : 8.0f;
        const float half = 0.5f * Lp;
        const float step = Lp * (1.0f / 15.0f);
        const float Brat = __expf(2.0f * cf * step * step);

        const int nrec = nclss + 1;
        if (tid < 3 * nrec) {                 // unit = (slot, axis), 16 ticks
            int slot = tid / 3;
            int ax   = tid - slot * 3;
            int isbase = (slot == nclss);
            int recid  = isbase ? 64 : slot;
            float dv   = isbase ? 0.0f : dsm[(int)ord[slot] * 3 + ax];
            float* dst = &tab[recid * 64 + ax * 16];

            float bse = -half - dv;
            int jc = __float2int_rn(-bse / step);   // tick nearest Gaussian peak
            jc = max(0, min(15, jc));
            float uc = bse + step * (float)jc;
            float fc = __expf(cf * uc * uc);
            float ru = __expf(cf * step * (2.0f * uc + step));
            float rd = __expf(cf * step * (step - 2.0f * uc));
            dst[jc] = fc;
            float f = fc, r = ru;
            for (int j = jc + 1; j < 16; j++) { f *= r; r *= Brat; dst[j] = f; }
            f = fc; r = rd;
            for (int j = jc - 1; j >= 0; j--) { f *= r; r *= Brat; dst[j] = f; }
        }
    }

    __syncthreads();

    // ---- Phase 2: consumer. Thread (y,z) accumulates x in [xq*4, xq*4+4) ----
    const char* tb = reinterpret_cast<const char*>(tab);
    const int offX = xq * 16;          // byte offset of this CTA's 4 x values
    const int offy = 64 + y * 4;
    const int offz = 128 + z * 4;

    const char* br = tb + 64 * 256;    // base record
    const float byz = *(const float*)(br + offy) * *(const float*)(br + offz);
    const ulonglong2 BX = *(const ulonglong2*)(br + offX);   // base X pairs (warp-uniform)

    // out offset (floats): (a*10 + t*2 + l)*4096 + x*256 + y*16 + z, x = xq*4..
    float* op = out + (((size_t)(a * 10 + l)) << 12) + ((size_t)xq << 10)
                    + ((size_t)y << 4) + (size_t)z;

    #pragma unroll
    for (int t = 0; t < 5; t++) {
        const int c = cntc[t];
        const u64 bw = pk2((float)(64 - c) * byz);
        u64 a0 = mul2(bw, BX.x);       // x pair (xq*4+0, xq*4+1)
        u64 a1 = mul2(bw, BX.y);       // x pair (xq*4+2, xq*4+3)

        const char* p = tb + startc[t] * 256;
        for (int k = 0; k < c; k++) {
            float wy = *(const float*)(p + offy);
            float wz = *(const float*)(p + offz);
            ulonglong2 X = *(const ulonglong2*)(p + offX);   // broadcast, 1 wf
            u64 w = pk2(wy * wz);
            a0 = fma2(w, X.x, a0);
            a1 = fma2(w, X.y, a1);
            p += 256;
        }

        float f0, f1, f2, f3;
        unpk(a0, f0, f1);
        unpk(a1, f2, f3);
        __stcs(op,       f0);          // each is a 128B-contiguous warp store
        __stcs(op + 256, f1);
        __stcs(op + 512, f2);
        __stcs(op + 768, f3);
        op += 2 * 4096;                // next type channel
    }
}

extern "C" void kernel_launch(void* const* d_in, const int* in_sizes, int n_in,
                              void* d_out, int out_size) {
    const float* dist = nullptr;
    const float* sig  = nullptr;
    const int*   an   = nullptr;
    for (int i = 0; i < n_in; i++) {
        if (in_sizes[i] == 1)          sig  = (const float*)d_in[i];
        else if (in_sizes[i] == 24576) dist = (const float*)d_in[i];
        else if (in_sizes[i] == 8192)  an   = (const int*)d_in[i];
    }
    if (!dist) dist = (const float*)d_in[0];
    if (!sig)  sig  = (const float*)d_in[1];
    if (!an)   an   = (const int*)d_in[2];

    mbv_kernel<<<1024, NT>>>(dist, sig, an, (float*)d_out);
}

// round 13
// speedup vs baseline: 1.0872x; 1.0136x over previous
#include <cuda_runtime.h>
#include <cstddef>

// ManyBodyVoxel: out[0, a, c=t*2+l, x, y, z] =
//   sum_n exp(coeff * || grid_l[x,y,z] - d[a,n]*mask_t[a,n] ||^2)
// R13: grid = 512 (a, l, zh) x 256 threads (y, z-in-half); each thread owns ALL
//      16 x of its (y,z) -> 8 packed x-accumulators, X rows warp-uniform
//      (2x LDS.128 broadcast). 11 instr / 16 voxel-updates in the hot loop.

#define NT 256

typedef unsigned long long u64;

__device__ __forceinline__ u64 pk2(float v) {
    u64 r; asm("mov.b64 %0, {%1, %2};" : "=l"(r) : "f"(v), "f"(v)); return r;
}
__device__ __forceinline__ u64 fma2(u64 a, u64 b, u64 c) {
    u64 d; asm("fma.rn.f32x2 %0, %1, %2, %3;" : "=l"(d) : "l"(a), "l"(b), "l"(c)); return d;
}
__device__ __forceinline__ u64 mul2(u64 a, u64 b) {
    u64 d; asm("mul.rn.f32x2 %0, %1, %2;" : "=l"(d) : "l"(a), "l"(b)); return d;
}
__device__ __forceinline__ void unpk(u64 v, float& lo, float& hi) {
    asm("mov.b64 {%0, %1}, %2;" : "=f"(lo), "=f"(hi) : "l"(v));
}

__global__ __launch_bounds__(NT, 8)
void mbv_kernel(const float* __restrict__ dist,   // (1,128,64,3) fp32
                const float* __restrict__ sigma,  // (1,) fp32
                const int*   __restrict__ anum,   // (128,64) int64 or int32 (auto-detect)
                float* __restrict__ out)          // (1,128,10,16,16,16) fp32
{
    const int b   = blockIdx.x;
    const int zh  = b & 1;            // z half
    const int l   = (b >> 1) & 1;     // 0: L=8, 1: L=12
    const int a   = b >> 2;
    const int tid = threadIdx.x;
    const int z   = zh * 8 + (tid & 7);
    const int y   = tid >> 3;         // wait: 256 threads = y(16) x z8(8) x 2?

    // NOTE: 256 threads = (y in 16) x (zi in 8) x (dup 2) would overcommit.
    // Use exactly 128 productive lanes? No -- remap: 256 = y(16) * zi(8) * s(2),
    // s splits the atom stream by parity and lane pairs combine at the end? Too
    // complex; instead: 256 threads = y(16) x zi(16) over FULL z, zh unused in
    // thread mapping, and zh splits the X dimension: this CTA covers x in
    // [zh*8, zh*8+8) (8 x-accumulators). Rename zh -> xh below.
    const int xh  = zh;               // x half: [xh*8, xh*8+8)
    const int zz  = tid & 15;         // z in [0,16)
    const int yy  = tid >> 4;         // y in [0,16)

    // Record (slot): 64 floats = 256B. x[16] @ +0, y[16] @ +64B, z[16] @ +128B.
    __shared__ __align__(16) float tab[65 * 64];
    __shared__ float dsm[192];
    __shared__ short ord[64];
    __shared__ int   startc[5];
    __shared__ int   cntc[5];
    __shared__ int   nclss;

    const float s  = sigma[0];
    const float cf = -0.5f / (s * s);

    // ---- Phase 0: warp0 classifies (ballot compaction); threads 32..223 stage dist ----
    if (tid < 32) {
        int4 p = ((const int4*)anum)[tid];            // probe row 0 (dtype)
        int4 q = ((const int4*)anum)[a * 32 + tid];   // int64 view
        int2 r = ((const int2*)anum)[a * 32 + tid];   // int32 view
        bool i32 = __any_sync(0xffffffffu, (p.y | p.w) != 0);
        int z0 = i32 ? r.x : q.x;
        int z1 = i32 ? r.y : q.z;
        unsigned lt = (1u << tid) - 1u;
        const int ZT[5] = {1, 6, 7, 8, 16};
        int base = 0;
        #pragma unroll
        for (int t = 0; t < 5; t++) {
            unsigned m0 = __ballot_sync(0xffffffffu, z0 == ZT[t]);
            unsigned m1 = __ballot_sync(0xffffffffu, z1 == ZT[t]);
            int c0 = __popc(m0), c = c0 + __popc(m1);
            if (z0 == ZT[t]) ord[base + __popc(m0 & lt)]      = (short)(2 * tid);
            if (z1 == ZT[t]) ord[base + c0 + __popc(m1 & lt)] = (short)(2 * tid + 1);
            if (tid == 0) { startc[t] = base; cntc[t] = c; }
            base += c;
        }
        if (tid == 0) nclss = base;
    } else if (tid < 224) {
        dsm[tid - 32] = dist[a * 192 + (tid - 32)];
    }

    __syncthreads();

    // ---- Phase 1: exp rows via center-out geometric recurrence ----
    {
        const float Lp   = l ? 12.0f : 8.0f;
        const float half = 0.5f * Lp;
        const float step = Lp * (1.0f / 15.0f);
        const float Brat = __expf(2.0f * cf * step * step);

        const int nrec = nclss + 1;
        if (tid < 3 * nrec) {                 // unit = (slot, axis), 16 ticks
            int slot = tid / 3;
            int ax   = tid - slot * 3;
            int isbase = (slot == nclss);
            int recid  = isbase ? 64 : slot;
            float dv   = isbase ? 0.0f : dsm[(int)ord[slot] * 3 + ax];
            float* dst = &tab[recid * 64 + ax * 16];

            float bse = -half - dv;
            int jc = __float2int_rn(-bse / step);
            jc = max(0, min(15, jc));
            float uc = bse + step * (float)jc;
            float fc = __expf(cf * uc * uc);
            float ru = __expf(cf * step * (2.0f * uc + step));
            float rd = __expf(cf * step * (step - 2.0f * uc));
            dst[jc] = fc;
            float f = fc, r = ru;
            for (int j = jc + 1; j < 16; j++) { f *= r; r *= Brat; dst[j] = f; }
            f = fc; r = rd;
            for (int j = jc - 1; j >= 0; j--) { f *= r; r *= Brat; dst[j] = f; }
        }
    }

    __syncthreads();

    // ---- Phase 2: consumer. Thread (yy,zz) accumulates x in [xh*8, xh*8+8) ----
    const char* tb = reinterpret_cast<const char*>(tab);
    const int offX = xh * 32;          // byte offset of this CTA's 8 x values
    const int offy = 64 + yy * 4;
    const int offz = 128 + zz * 4;

    const char* br = tb + 64 * 256;    // base record
    const float byz = *(const float*)(br + offy) * *(const float*)(br + offz);
    const ulonglong2 BXa = *(const ulonglong2*)(br + offX);
    const ulonglong2 BXb = *(const ulonglong2*)(br + offX + 16);

    // out offset (floats): (a*10 + t*2 + l)*4096 + x*256 + y*16 + z, x = xh*8..
    float* op = out + (((size_t)(a * 10 + l)) << 12) + ((size_t)xh << 11)
                    + ((size_t)yy << 4) + (size_t)zz;

    #pragma unroll
    for (int t = 0; t < 5; t++) {
        const int c = cntc[t];
        const u64 bw = pk2((float)(64 - c) * byz);
        u64 a0 = mul2(bw, BXa.x);
        u64 a1 = mul2(bw, BXa.y);
        u64 a2 = mul2(bw, BXb.x);
        u64 a3 = mul2(bw, BXb.y);

        const char* p = tb + startc[t] * 256;
        for (int k = 0; k < c; k++) {
            float wy = *(const float*)(p + offy);
            float wz = *(const float*)(p + offz);
            ulonglong2 Xa = *(const ulonglong2*)(p + offX);        // uniform, 1 wf
            ulonglong2 Xb = *(const ulonglong2*)(p + offX + 16);   // uniform, 1 wf
            u64 w = pk2(wy * wz);
            a0 = fma2(w, Xa.x, a0);
            a1 = fma2(w, Xa.y, a1);
            a2 = fma2(w, Xb.x, a2);
            a3 = fma2(w, Xb.y, a3);
            p += 256;
        }

        float f0, f1, f2, f3, f4, f5, f6, f7;
        unpk(a0, f0, f1); unpk(a1, f2, f3);
        unpk(a2, f4, f5); unpk(a3, f6, f7);
        __stcs(op,        f0);
        __stcs(op +  256, f1);
        __stcs(op +  512, f2);
        __stcs(op +  768, f3);
        __stcs(op + 1024, f4);
        __stcs(op + 1280, f5);
        __stcs(op + 1536, f6);
        __stcs(op + 1792, f7);
        op += 2 * 4096;                // next type channel
    }
}

extern "C" void kernel_launch(void* const* d_in, const int* in_sizes, int n_in,
                              void* d_out, int out_size) {
    const float* dist = nullptr;
    const float* sig  = nullptr;
    const int*   an   = nullptr;
    for (int i = 0; i < n_in; i++) {
        if (in_sizes[i] == 1)          sig  = (const float*)d_in[i];
        else if (in_sizes[i] == 24576) dist = (const float*)d_in[i];
        else if (in_sizes[i] == 8192)  an   = (const int*)d_in[i];
    }
    if (!dist) dist = (const float*)d_in[0];
    if (!sig)  sig  = (const float*)d_in[1];
    if (!an)   an   = (const int*)d_in[2];

    mbv_kernel<<<512, NT>>>(dist, sig, an, (float*)d_out);
}